// round 4
// baseline (speedup 1.0000x reference)
#include <cuda_runtime.h>
#include <cuda_bf16.h>
#include <cstdint>

// Problem constants
#define NUM_CHIPS 4
#define SEQ 1024
#define HIDDEN 2048
#define TOP_K 4
#define N_EXPERTS 32
#define MAX_TOK 1024
#define META_LEN 8
#define N_PER_CHIP (SEQ * TOP_K)           // 4096 assignments per chip
#define N_TOTAL (NUM_CHIPS * N_PER_CHIP)   // 16384 assignments
#define N_CHUNKS (N_TOTAL / 32)            // 512 warp-chunks (chip-major order)
#define CHUNKS_PER_LANE (N_CHUNKS / 32)    // 16
#define TOTAL_SLOTS (N_EXPERTS * MAX_TOK)  // 32768
#define BUF_ELEMS ((size_t)TOTAL_SLOTS * HIDDEN)      // 67108864
#define META_OFF  BUF_ELEMS
#define CNT_OFF   (BUF_ELEMS + (size_t)TOTAL_SLOTS * META_LEN)

// Scratch (no allocations allowed)
__device__ int g_src[TOTAL_SLOTS];                    // slot -> assignment id (only [0,cnt_e) valid)
__device__ int g_rank[N_TOTAL];                       // rank within warp-chunk's expert group
__device__ int g_wcount[N_EXPERTS][N_CHUNKS];         // per-expert per-chunk counts
__device__ int g_chunk_off[N_EXPERTS][N_CHUNKS];      // exclusive chunk offset within expert
__device__ int g_cnt[N_EXPERTS];                      // total per-expert count

// ---------------------------------------------------------------------------
// Kernel A: per-warp-chunk expert counts + stable within-chunk rank via
// __match_any_sync. No g_src init needed (gather uses cnt_e to gate reads).
// ---------------------------------------------------------------------------
__global__ void __launch_bounds__(1024) rank_count_kernel(const int* __restrict__ idx) {
    const int a    = blockIdx.x * 1024 + threadIdx.x;  // chip-major assignment id
    const int lane = threadIdx.x & 31;
    const int wchunk = a >> 5;

    g_wcount[lane][wchunk] = 0;          // zero this chunk's 32-expert column
    __syncwarp();

    const int v = idx[a];
    const unsigned m  = __match_any_sync(0xFFFFFFFFu, v);
    const unsigned lt = (1u << lane) - 1u;
    g_rank[a] = __popc(m & lt);
    if ((m & lt) == 0)                    // lowest lane of each expert group
        g_wcount[v][wchunk] = __popc(m);
}

// ---------------------------------------------------------------------------
// Kernel B (single block, 1024 threads): two-level scan + plan, fused.
// Phase 1: warp e scans expert e's 512 chunk counts (lane owns 16 contiguous
//          chunks; one warp shuffle-scan of local sums). Emits chunk offsets,
//          per-expert totals, and the 32 output counters.
// Phase 2: all 1024 threads compute slots for the 16384 assignments and
//          write the inverse map.
// ---------------------------------------------------------------------------
__global__ void __launch_bounds__(1024) scan_plan_kernel(const int* __restrict__ idx,
                                                         float* __restrict__ out) {
    const int e    = threadIdx.x >> 5;
    const int lane = threadIdx.x & 31;

    // Phase 1: two-level exclusive scan over this expert's 512 chunk counts.
    int cnt[CHUNKS_PER_LANE];
    const int4* wc = reinterpret_cast<const int4*>(&g_wcount[e][lane * CHUNKS_PER_LANE]);
    int4 c0 = wc[0], c1 = wc[1], c2 = wc[2], c3 = wc[3];
    cnt[0]=c0.x; cnt[1]=c0.y; cnt[2]=c0.z; cnt[3]=c0.w;
    cnt[4]=c1.x; cnt[5]=c1.y; cnt[6]=c1.z; cnt[7]=c1.w;
    cnt[8]=c2.x; cnt[9]=c2.y; cnt[10]=c2.z; cnt[11]=c2.w;
    cnt[12]=c3.x; cnt[13]=c3.y; cnt[14]=c3.z; cnt[15]=c3.w;

    int lsum = 0;
#pragma unroll
    for (int j = 0; j < CHUNKS_PER_LANE; j++) lsum += cnt[j];

    int s = lsum;
#pragma unroll
    for (int d = 1; d < 32; d <<= 1) {
        int t = __shfl_up_sync(0xFFFFFFFFu, s, d);
        if (lane >= d) s += t;
    }
    int base = s - lsum;                               // exclusive prefix of lane sums
    int total = __shfl_sync(0xFFFFFFFFu, s, 31);

    int run = base;
#pragma unroll
    for (int j = 0; j < CHUNKS_PER_LANE; j++) {
        g_chunk_off[e][lane * CHUNKS_PER_LANE + j] = run;
        run += cnt[j];
    }
    if (lane == 0) {
        g_cnt[e] = total;
        out[CNT_OFF + e] = (float)total;
    }
    __syncthreads();

    // Phase 2: plan — inverse map.
#pragma unroll
    for (int i = 0; i < N_TOTAL / 1024; i++) {
        const int a  = i * 1024 + threadIdx.x;
        const int ex = idx[a];
        const int slot = ex * MAX_TOK + g_chunk_off[ex][a >> 5] + g_rank[a];
        g_src[slot] = a;
    }
}

// ---------------------------------------------------------------------------
// Kernel C: one block per slot; copy token row (or zeros) + 8 meta words.
// Streaming stores (evict-first): output is written once, never re-read.
// ---------------------------------------------------------------------------
__global__ void __launch_bounds__(256) gather_kernel(const float* __restrict__ x,
                                                     const float* __restrict__ w,
                                                     const int* __restrict__ indices,
                                                     float* __restrict__ out) {
    const int slot = blockIdx.x;
    const int e    = slot >> 10;
    const int si   = slot & (MAX_TOK - 1);
    const int t    = threadIdx.x;
    float4* dst = reinterpret_cast<float4*>(out + (size_t)slot * HIDDEN);
    float4* md  = reinterpret_cast<float4*>(out + META_OFF + (size_t)slot * META_LEN);

    if (si < g_cnt[e]) {
        const int a   = g_src[slot];
        const int c   = a >> 12;
        const int n   = a & (N_PER_CHIP - 1);
        const int tok = n >> 2;
        const float4* src =
            reinterpret_cast<const float4*>(x + ((size_t)c * SEQ + tok) * HIDDEN);
        float4 v0 = src[t];
        float4 v1 = src[t + 256];
        __stcs(dst + t,       v0);
        __stcs(dst + t + 256, v1);
        if (t == 0) {
            __nv_bfloat16 hb = __float2bfloat16(w[a]);
            unsigned short bits = __bfloat16_as_ushort(hb);
            __stcs(md,     make_float4((float)c, (float)tok, (float)(n & 3), (float)e));
            __stcs(md + 1, make_float4((float)bits, 0.f, 0.f, 0.f));
        }
    } else {
        const float4 z = make_float4(0.f, 0.f, 0.f, 0.f);
        __stcs(dst + t,       z);
        __stcs(dst + t + 256, z);
        if (t == 0) {
            const float4 neg = make_float4(-1.f, -1.f, -1.f, -1.f);
            __stcs(md,     neg);
            __stcs(md + 1, neg);
        }
    }
}

// ---------------------------------------------------------------------------
extern "C" void kernel_launch(void* const* d_in, const int* in_sizes, int n_in,
                              void* d_out, int out_size) {
    const float* x   = (const float*)d_in[0];   // [4,1024,2048] f32
    const float* wts = (const float*)d_in[1];   // [4,1024,4]    f32
    const int*   ind = (const int*)  d_in[2];   // [4,1024,4]    i32
    float* out = (float*)d_out;

    rank_count_kernel<<<N_TOTAL / 1024, 1024>>>(ind);
    scan_plan_kernel<<<1, 1024>>>(ind, out);
    gather_kernel<<<TOTAL_SLOTS, 256>>>(x, wts, ind, out);
}